// round 14
// baseline (speedup 1.0000x reference)
#include <cuda_runtime.h>
#include <cstdint>
#include <math.h>

// Problem constants
#define Bb 4
#define Ss 2048
#define Ee 1024
#define Hh 16
#define Dd 64
#define Mm (Bb*Ss)      // 8192
#define Nn (Hh*Dd)      // 1024

// q scale folded with log2(e): exp(s*0.125) = 2^(s*0.125*log2e)
#define QSCL 0.18033688011112042f

// Scratch (device globals: allocation-free, graph-capture safe)
// q: A-frag tiles  [bh][s/16][d/8][128]   (pre-scaled by QSCL)
// k: B-frag tiles  [bh][s/8][d/8][64]
// v: B-frag tiles  [bh][d/8][t/8][64]     (n=d, k=t)
// z: A-frag tiles  [bh][s/16][d/8][128]   (NEW: frag-ordered for outproj)
__device__ float g_q[(size_t)Bb*Hh*Ss*Dd];
__device__ float g_k[(size_t)Bb*Hh*Ss*Dd];
__device__ float g_v[(size_t)Bb*Hh*Ss*Dd];
__device__ float g_z[(size_t)Bb*Hh*Ss*Dd];
// Fragment-tile-ordered GEMM operands (produced by round_all)
__device__ float g_xr[(size_t)Mm*Ee];        // [m/16][e/8][128]
__device__ float g_wqr[(size_t)Hh*Ee*Dd];    // [n/8][e/8][64], n=h*64+d
__device__ float g_wkr[(size_t)Hh*Ee*Dd];
__device__ float g_wvr[(size_t)Hh*Ee*Dd];
__device__ float g_wor[(size_t)Nn*Ee];       // [e/8][hd/8][64]

// ---------------------------------------------------------------------------
// Helpers
// ---------------------------------------------------------------------------
__device__ __forceinline__ float tf32r(float x) {
    float y; asm("cvt.rna.tf32.f32 %0, %1;" : "=f"(y) : "f"(x)); return y;
}
__device__ __forceinline__ float ex2(float x) {
    float y; asm("ex2.approx.f32 %0, %1;" : "=f"(y) : "f"(x)); return y;
}
__device__ __forceinline__ float4 cvt4(float4 v) {
    v.x = tf32r(v.x); v.y = tf32r(v.y); v.z = tf32r(v.z); v.w = tf32r(v.w);
    return v;
}
__device__ __forceinline__ void mma_tf32(float* d, const uint32_t* a,
                                         const uint32_t* b) {
    asm volatile(
        "mma.sync.aligned.m16n8k8.row.col.f32.tf32.tf32.f32 "
        "{%0,%1,%2,%3}, {%4,%5,%6,%7}, {%8,%9}, {%0,%1,%2,%3};"
        : "+f"(d[0]), "+f"(d[1]), "+f"(d[2]), "+f"(d[3])
        : "r"(a[0]), "r"(a[1]), "r"(a[2]), "r"(a[3]), "r"(b[0]), "r"(b[1]));
}
__device__ __forceinline__ uint32_t smem_u32(const void* p) {
    uint32_t a;
    asm("{ .reg .u64 t; cvta.to.shared.u64 t, %1; cvt.u32.u64 %0, t; }"
        : "=r"(a) : "l"(p));
    return a;
}
__device__ __forceinline__ void cpa(uint32_t dst, const void* src) {
    asm volatile("cp.async.cg.shared.global [%0], [%1], 16;"
                 :: "r"(dst), "l"(src));
}
__device__ __forceinline__ void cp_commit() {
    asm volatile("cp.async.commit_group;");
}
template<int N> __device__ __forceinline__ void cp_wait() {
    asm volatile("cp.async.wait_group %0;" :: "n"(N));
}

// ---------------------------------------------------------------------------
// Merged pre-round + fragment-swizzle pass (unchanged).
// ---------------------------------------------------------------------------
#define NX4 (Mm*Ee/4)
#define NW4 (Hh*Ee*Dd/4)
__global__ __launch_bounds__(256)
void round_all(const float4* __restrict__ x,  const float4* __restrict__ wq,
               const float4* __restrict__ wk, const float4* __restrict__ wv,
               const float4* __restrict__ wo)
{
    int i = blockIdx.x * 256 + threadIdx.x;
    if (i < NX4) {
        float4 v = cvt4(x[i]);
        const int m = (i << 2) >> 10;
        const int k = (i << 2) & 1023;
        float* p = g_xr + ((size_t)(m >> 4) * (Ee >> 3) + (k >> 3)) * 128
                 + ((m & 7) * 4) * 4 + ((m >> 3) & 1) + 2 * ((k >> 2) & 1);
        p[0] = v.x; p[4] = v.y; p[8] = v.z; p[12] = v.w;
        return;
    }
    i -= NX4;
    const int seg = i >> 18;
    const int j = i & (NW4 - 1);
    if (seg < 3) {
        const float4 v = cvt4(seg == 0 ? wq[j] : (seg == 1 ? wk[j] : wv[j]));
        float* dst = seg == 0 ? g_wqr : (seg == 1 ? g_wkr : g_wvr);
        const int elem = j << 2;
        const int h = elem >> 16;
        const int rem = elem & 65535;
        const int k = rem >> 6;
        const int n = h * 64 + (rem & 63);
        float* p = dst + ((size_t)(n >> 3) * (Ee >> 3) + (k >> 3)) * 64
                 + ((n & 7) * 4 + (k & 3)) * 2 + ((k >> 2) & 1);
        p[0] = v.x; p[8] = v.y; p[16] = v.z; p[24] = v.w;
    } else {
        const float4 v = cvt4(wo[j]);
        const int elem = j << 2;
        const int k = elem >> 10;
        const int n = elem & 1023;
        float* p = g_wor + ((size_t)(n >> 3) * (Nn >> 3) + (k >> 3)) * 64
                 + ((n & 7) * 4 + (k & 3)) * 2 + ((k >> 2) & 1);
        p[0] = v.x; p[8] = v.y; p[16] = v.z; p[24] = v.w;
    }
}

// ---------------------------------------------------------------------------
// GEMM config (both GEMMs now identical structure)
// ---------------------------------------------------------------------------
#define KC 32
#define ABYTES 16384
#define BBYTES 16384
#define STG (ABYTES+BBYTES)
#define GEMM_SMEM (3*STG)

// ---------------------------------------------------------------------------
// Kernel 1: QKV projection (unchanged; writes q/k/v in frag-tile order)
// ---------------------------------------------------------------------------
__global__ __launch_bounds__(256, 2)
void proj_mma(const float* __restrict__ bq, const float* __restrict__ bk,
              const float* __restrict__ bv)
{
    extern __shared__ float sm[];
    const uint32_t sb = smem_u32(sm);
    const int sel = blockIdx.z;
    const float* W    = sel == 0 ? g_wqr : (sel == 1 ? g_wkr : g_wvr);
    const float* bias = sel == 0 ? bq    : (sel == 1 ? bk    : bv);

    const int t = threadIdx.x, lane = t & 31, wid = t >> 5;
    const int q = lane & 3, g = lane >> 2;
    const int wm4 = (wid & 1) * 4;
    const int wn4 = (wid >> 1) * 4;
    const int n0 = blockIdx.x * 128, m0 = blockIdx.y * 128;

    float acc[4][4][4];
    #pragma unroll
    for (int i = 0; i < 4; i++)
        #pragma unroll
        for (int j = 0; j < 4; j++)
            #pragma unroll
            for (int kk = 0; kk < 4; kk++) acc[i][j][kk] = 0.f;

    auto issue = [&](int k0, int s) {
        const uint32_t Ab = sb + s * STG;
        const uint32_t Bbse = Ab + ABYTES;
        #pragma unroll
        for (int j = 0; j < 4; j++) {
            const int idx = t + 256 * j;
            const int aseg = idx >> 7, aoff = idx & 127;
            cpa(Ab + idx * 16,
                g_xr + ((size_t)((m0 >> 4) + aseg) * (Ee >> 3) + (k0 >> 3)) * 128
                     + aoff * 4);
            const int bseg = idx >> 6, boff = idx & 63;
            cpa(Bbse + idx * 16,
                W + ((size_t)((n0 >> 3) + bseg) * (Ee >> 3) + (k0 >> 3)) * 64
                  + boff * 4);
        }
        cp_commit();
    };
    auto compute = [&](int s) {
        const uint32_t* A = (const uint32_t*)(sm + s * (STG / 4));
        const uint32_t* B = A + ABYTES / 4;
        #pragma unroll
        for (int ks = 0; ks < 4; ks++) {
            uint4 a4[4];
            #pragma unroll
            for (int mt = 0; mt < 4; mt++)
                a4[mt] = *(const uint4*)(A + ((wm4 + mt) * 4 + ks) * 128 + lane * 4);
            #pragma unroll
            for (int nt = 0; nt < 4; nt++) {
                const uint2 b2 = *(const uint2*)(B + ((wn4 + nt) * 4 + ks) * 64 + lane * 2);
                const uint32_t bf[2] = {b2.x, b2.y};
                #pragma unroll
                for (int mt = 0; mt < 4; mt++)
                    mma_tf32(acc[mt][nt], (const uint32_t*)&a4[mt], bf);
            }
        }
    };

    const int NC = Ee / KC;
    issue(0, 0);
    issue(KC, 1);
    for (int c = 0; c < NC; c++) {
        if (c + 1 < NC) cp_wait<1>(); else cp_wait<0>();
        __syncthreads();
        if (c + 2 < NC) issue((c + 2) * KC, (c + 2) % 3);
        compute(c % 3);
    }

    #pragma unroll
    for (int mt = 0; mt < 4; mt++) {
        #pragma unroll
        for (int rr = 0; rr < 2; rr++) {
            const int r_g = m0 + (wid & 1) * 64 + mt * 16 + g + rr * 8;
            const int bi = r_g >> 11, s = r_g & 2047;
            #pragma unroll
            for (int nt = 0; nt < 4; nt++) {
                const int n_g = n0 + (wid >> 1) * 32 + nt * 8 + 2 * q;
                const int h = n_g >> 6, d = n_g & 63;
                const size_t bh_off = (size_t)(bi * Hh + h) * Ss * Dd;
                float vx = acc[mt][nt][2*rr + 0] + bias[n_g];
                float vy = acc[mt][nt][2*rr + 1] + bias[n_g + 1];
                if (sel == 0) {
                    float* p = g_q + bh_off
                        + ((size_t)(s >> 4) * (Dd >> 3) + (d >> 3)) * 128
                        + ((s & 7) * 4 + (d & 3)) * 4 + ((s >> 3) & 1)
                        + 2 * ((d >> 2) & 1);
                    p[0] = tf32r(vx * QSCL);
                    p[4] = tf32r(vy * QSCL);
                } else if (sel == 1) {
                    float* p = g_k + bh_off
                        + ((size_t)(s >> 3) * (Dd >> 3) + (d >> 3)) * 64
                        + ((s & 7) * 4 + (d & 3)) * 2 + ((d >> 2) & 1);
                    p[0] = tf32r(vx);
                    p[2] = tf32r(vy);
                } else {
                    float* p = g_v + bh_off
                        + ((size_t)(d >> 3) * (Ss >> 3) + (s >> 3)) * 64
                        + ((d & 7) * 4 + (s & 3)) * 2 + ((s >> 2) & 1);
                    p[0] = tf32r(vx);
                    p[8] = tf32r(vy);
                }
            }
        }
    }
}

// ---------------------------------------------------------------------------
// Kernel 3: output projection — A now frag-ordered from g_z (clone of proj).
// ---------------------------------------------------------------------------
__global__ __launch_bounds__(256, 2)
void outproj_mma(const float* __restrict__ bo, float* __restrict__ outp)
{
    extern __shared__ float sm[];
    const uint32_t sb = smem_u32(sm);
    const int t = threadIdx.x, lane = t & 31, wid = t >> 5;
    const int q = lane & 3, g = lane >> 2;
    const int wm4 = (wid & 1) * 4;
    const int wn4 = (wid >> 1) * 4;
    const int e0 = blockIdx.x * 128, m0 = blockIdx.y * 128;
    const int bi = m0 >> 11, s0 = m0 & 2047;

    float acc[4][4][4];
    #pragma unroll
    for (int i = 0; i < 4; i++)
        #pragma unroll
        for (int j = 0; j < 4; j++)
            #pragma unroll
            for (int kk = 0; kk < 4; kk++) acc[i][j][kk] = 0.f;

    auto issue = [&](int k0, int s) {
        const uint32_t Ab = sb + s * STG;
        const uint32_t Bbse = Ab + ABYTES;
        const int h = k0 >> 6, d0 = k0 & 63;
        const float* zb = g_z + (size_t)(bi * Hh + h) * Ss * Dd;
        #pragma unroll
        for (int j = 0; j < 4; j++) {
            const int idx = t + 256 * j;
            // A: 8 mtiles x 512 floats; 4 d-tiles contiguous in frag layout
            const int aseg = idx >> 7, aoff = idx & 127;
            cpa(Ab + idx * 16,
                zb + ((size_t)(((s0 >> 4) + aseg) * (Dd >> 3)) + (d0 >> 3)) * 128
                   + aoff * 4);
            const int bseg = idx >> 6, boff = idx & 63;
            cpa(Bbse + idx * 16,
                g_wor + ((size_t)((e0 >> 3) + bseg) * (Nn >> 3) + (k0 >> 3)) * 64
                      + boff * 4);
        }
        cp_commit();
    };
    auto compute = [&](int s) {
        const uint32_t* A = (const uint32_t*)(sm + s * (STG / 4));
        const uint32_t* B = A + ABYTES / 4;
        #pragma unroll
        for (int ks = 0; ks < 4; ks++) {
            uint4 a4[4];
            #pragma unroll
            for (int mt = 0; mt < 4; mt++)
                a4[mt] = *(const uint4*)(A + ((wm4 + mt) * 4 + ks) * 128 + lane * 4);
            #pragma unroll
            for (int nt = 0; nt < 4; nt++) {
                const uint2 b2 = *(const uint2*)(B + ((wn4 + nt) * 4 + ks) * 64 + lane * 2);
                const uint32_t bf[2] = {b2.x, b2.y};
                #pragma unroll
                for (int mt = 0; mt < 4; mt++)
                    mma_tf32(acc[mt][nt], (const uint32_t*)&a4[mt], bf);
            }
        }
    };

    const int NC = Nn / KC;
    issue(0, 0);
    issue(KC, 1);
    for (int c = 0; c < NC; c++) {
        if (c + 1 < NC) cp_wait<1>(); else cp_wait<0>();
        __syncthreads();
        if (c + 2 < NC) issue((c + 2) * KC, (c + 2) % 3);
        compute(c % 3);
    }

    #pragma unroll
    for (int mt = 0; mt < 4; mt++) {
        #pragma unroll
        for (int rr = 0; rr < 2; rr++) {
            const int r_g = m0 + (wid & 1) * 64 + mt * 16 + g + rr * 8;
            #pragma unroll
            for (int nt = 0; nt < 4; nt++) {
                const int e = e0 + (wid >> 1) * 32 + nt * 8 + 2 * q;
                float2 v;
                v.x = acc[mt][nt][2*rr + 0] + bo[e];
                v.y = acc[mt][nt][2*rr + 1] + bo[e + 1];
                *(float2*)(outp + (size_t)r_g * Ee + e) = v;
            }
        }
    }
}

// ---------------------------------------------------------------------------
// Kernel 2: flash attention, 2 CTAs/SM (unchanged loop);
// epilogue now writes z in A-frag tile order.
// ---------------------------------------------------------------------------
#define APITCH 68
#define AROWS 128
#define PFL (AROWS*APITCH)         // 8704 floats
#define KVT 4096
#define FO_P  0
#define FO_K0 PFL
#define FO_V0 (FO_K0 + KVT)
#define FO_K1 (FO_V0 + KVT)
#define FO_V1 (FO_K1 + KVT)
#define ATTN_SMEM ((PFL + 4*KVT)*4)   // 100352 bytes

__global__ __launch_bounds__(256, 2)
void attn_mma()
{
    extern __shared__ float sm[];
    const uint32_t sb = smem_u32(sm);
    const int t = threadIdx.x, lane = t & 31, wid = t >> 5;
    const int q = lane & 3, g = lane >> 2;
    const int bh = blockIdx.y;
    const int row0 = blockIdx.x * AROWS;
    const size_t bhoff = (size_t)bh * Ss * Dd;
    const int wr = wid * 16;

    uint32_t* Pu = (uint32_t*)sm + FO_P;
    float* Ps = sm + FO_P;

    auto issueKV = [&](int t0, int s) {
        const uint32_t Kb = sb + (s ? FO_K1 : FO_K0) * 4;
        const uint32_t Vb = sb + (s ? FO_V1 : FO_V0) * 4;
        #pragma unroll
        for (int j = 0; j < 4; j++) {
            const int idx = t + 256 * j;
            cpa(Kb + idx * 16, g_k + bhoff + (size_t)t0 * 64 + idx * 4);
            const int dt = idx >> 7, rem = idx & 127;
            cpa(Vb + idx * 16,
                g_v + bhoff + ((size_t)dt * (Ss >> 3) + (t0 >> 3)) * 64 + rem * 4);
        }
        cp_commit();
    };

    // Q fragments straight into registers
    uint4 qf[8];
    {
        const float* qb = g_q + bhoff + (size_t)((row0 >> 4) + wid) * 8 * 128;
        #pragma unroll
        for (int ks = 0; ks < 8; ks++)
            qf[ks] = *(const uint4*)(qb + ks * 128 + lane * 4);
    }

    issueKV(0, 0);

    float lR[2] = {0.f, 0.f};
    float o[8][4];
    #pragma unroll
    for (int nt = 0; nt < 8; nt++)
        #pragma unroll
        for (int c = 0; c < 4; c++) o[nt][c] = 0.f;

    const int NT = Ss / 64;
    for (int it = 0; it < NT; it++) {
        cp_wait<0>();
        __syncthreads();
        const int buf = it & 1;
        if (it + 1 < NT) issueKV((it + 1) * 64, buf ^ 1);

        const uint32_t* Ku = (const uint32_t*)sm + (buf ? FO_K1 : FO_K0);
        const uint32_t* Vu = (const uint32_t*)sm + (buf ? FO_V1 : FO_V0);

        float s[8][4];
        #pragma unroll
        for (int nt = 0; nt < 8; nt++)
            #pragma unroll
            for (int c = 0; c < 4; c++) s[nt][c] = 0.f;
        #pragma unroll
        for (int ks = 0; ks < 8; ks++) {
            #pragma unroll
            for (int nt = 0; nt < 8; nt++) {
                const uint2 b2 = *(const uint2*)(Ku + (nt * 8 + ks) * 64 + lane * 2);
                const uint32_t bf[2] = {b2.x, b2.y};
                mma_tf32(s[nt], (const uint32_t*)&qf[ks], bf);
            }
        }

        #pragma unroll
        for (int rr = 0; rr < 2; rr++) {
            const int prow = wr + rr * 8 + g;
            float sum = 0.f;
            #pragma unroll
            for (int nt = 0; nt < 8; nt++) {
                float p0 = tf32r(ex2(s[nt][2*rr]));
                float p1 = tf32r(ex2(s[nt][2*rr+1]));
                sum += p0 + p1;
                float2 v; v.x = p0; v.y = p1;
                *(float2*)(Ps + prow * APITCH + nt * 8 + 2 * q) = v;
            }
            lR[rr] += sum;
        }
        __syncwarp();

        #pragma unroll
        for (int ks = 0; ks < 8; ks++) {
            const int ko = ks * 8;
            uint32_t af[4];
            af[0] = Pu[(wr + g) * APITCH + ko + q];
            af[1] = Pu[(wr + 8 + g) * APITCH + ko + q];
            af[2] = Pu[(wr + g) * APITCH + ko + q + 4];
            af[3] = Pu[(wr + 8 + g) * APITCH + ko + q + 4];
            #pragma unroll
            for (int nt = 0; nt < 8; nt++) {
                const uint2 b2 = *(const uint2*)(Vu + (nt * 8 + ks) * 64 + lane * 2);
                const uint32_t bf[2] = {b2.x, b2.y};
                mma_tf32(o[nt], af, bf);
            }
        }
    }

    // Reduce denominators, normalize, write z in A-FRAG tile order
    #pragma unroll
    for (int i = 0; i < 2; i++) {
        lR[i] += __shfl_xor_sync(0xffffffffu, lR[i], 1);
        lR[i] += __shfl_xor_sync(0xffffffffu, lR[i], 2);
    }
    #pragma unroll
    for (int rr = 0; rr < 2; rr++) {
        const float inv = 1.0f / lR[rr];
        const int s = row0 + wr + rr * 8 + g;
        #pragma unroll
        for (int nt = 0; nt < 8; nt++) {
            const int d = nt * 8 + 2 * q;
            float* p = g_z + bhoff
                + ((size_t)(s >> 4) * (Dd >> 3) + (d >> 3)) * 128
                + ((s & 7) * 4 + (d & 3)) * 4 + ((s >> 3) & 1)
                + 2 * ((d >> 2) & 1);
            p[0] = tf32r(o[nt][2*rr]   * inv);
            p[4] = tf32r(o[nt][2*rr+1] * inv);
        }
    }
}

// ---------------------------------------------------------------------------
extern "C" void kernel_launch(void* const* d_in, const int* in_sizes, int n_in,
                              void* d_out, int out_size)
{
    const float* x  = (const float*)d_in[0];
    const float* Wq = (const float*)d_in[1];
    const float* bq = (const float*)d_in[2];
    const float* Wk = (const float*)d_in[3];
    const float* bk = (const float*)d_in[4];
    const float* Wv = (const float*)d_in[5];
    const float* bv = (const float*)d_in[6];
    const float* Wo = (const float*)d_in[7];
    const float* bo = (const float*)d_in[8];
    float* out = (float*)d_out;

    cudaFuncSetAttribute(proj_mma,
                         cudaFuncAttributeMaxDynamicSharedMemorySize, GEMM_SMEM);
    cudaFuncSetAttribute(outproj_mma,
                         cudaFuncAttributeMaxDynamicSharedMemorySize, GEMM_SMEM);
    cudaFuncSetAttribute(attn_mma,
                         cudaFuncAttributeMaxDynamicSharedMemorySize, ATTN_SMEM);

    const int ntot = NX4 + 4 * NW4;
    round_all<<<(ntot + 255)/256, 256>>>((const float4*)x, (const float4*)Wq,
                                         (const float4*)Wk, (const float4*)Wv,
                                         (const float4*)Wo);

    proj_mma<<<dim3(Nn/128, Mm/128, 3), 256, GEMM_SMEM>>>(bq, bk, bv);
    attn_mma<<<dim3(Ss/AROWS, Bb*Hh), 256, ATTN_SMEM>>>();
    outproj_mma<<<dim3(Ee/128, Mm/128), 256, GEMM_SMEM>>>(bo, out);
}

// round 15
// speedup vs baseline: 1.5500x; 1.5500x over previous
#include <cuda_runtime.h>
#include <cstdint>
#include <math.h>

// Problem constants
#define Bb 4
#define Ss 2048
#define Ee 1024
#define Hh 16
#define Dd 64
#define Mm (Bb*Ss)      // 8192
#define Nn (Hh*Dd)      // 1024

// q scale folded with log2(e): exp(s*0.125) = 2^(s*0.125*log2e)
#define QSCL 0.18033688011112042f

// Scratch (device globals: allocation-free, graph-capture safe)
// q: A-frag tiles  [bh][s/16][d/8][128]   (pre-scaled by QSCL)
// k: B-frag tiles  [bh][s/8][d/8][64]
// v: B-frag tiles  [bh][d/8][t/8][64]     (n=d, k=t)
// z: A-frag tiles  [bh][s/16][d/8][128]   (written coalesced via smem staging)
__device__ float g_q[(size_t)Bb*Hh*Ss*Dd];
__device__ float g_k[(size_t)Bb*Hh*Ss*Dd];
__device__ float g_v[(size_t)Bb*Hh*Ss*Dd];
__device__ float g_z[(size_t)Bb*Hh*Ss*Dd];
// Fragment-tile-ordered GEMM operands (produced by round_all)
__device__ float g_xr[(size_t)Mm*Ee];        // [m/16][e/8][128]
__device__ float g_wqr[(size_t)Hh*Ee*Dd];    // [n/8][e/8][64], n=h*64+d
__device__ float g_wkr[(size_t)Hh*Ee*Dd];
__device__ float g_wvr[(size_t)Hh*Ee*Dd];
__device__ float g_wor[(size_t)Nn*Ee];       // [e/8][hd/8][64]

// ---------------------------------------------------------------------------
// Helpers
// ---------------------------------------------------------------------------
__device__ __forceinline__ float tf32r(float x) {
    float y; asm("cvt.rna.tf32.f32 %0, %1;" : "=f"(y) : "f"(x)); return y;
}
__device__ __forceinline__ float ex2(float x) {
    float y; asm("ex2.approx.f32 %0, %1;" : "=f"(y) : "f"(x)); return y;
}
__device__ __forceinline__ float4 cvt4(float4 v) {
    v.x = tf32r(v.x); v.y = tf32r(v.y); v.z = tf32r(v.z); v.w = tf32r(v.w);
    return v;
}
__device__ __forceinline__ void mma_tf32(float* d, const uint32_t* a,
                                         const uint32_t* b) {
    asm volatile(
        "mma.sync.aligned.m16n8k8.row.col.f32.tf32.tf32.f32 "
        "{%0,%1,%2,%3}, {%4,%5,%6,%7}, {%8,%9}, {%0,%1,%2,%3};"
        : "+f"(d[0]), "+f"(d[1]), "+f"(d[2]), "+f"(d[3])
        : "r"(a[0]), "r"(a[1]), "r"(a[2]), "r"(a[3]), "r"(b[0]), "r"(b[1]));
}
__device__ __forceinline__ uint32_t smem_u32(const void* p) {
    uint32_t a;
    asm("{ .reg .u64 t; cvta.to.shared.u64 t, %1; cvt.u32.u64 %0, t; }"
        : "=r"(a) : "l"(p));
    return a;
}
__device__ __forceinline__ void cpa(uint32_t dst, const void* src) {
    asm volatile("cp.async.cg.shared.global [%0], [%1], 16;"
                 :: "r"(dst), "l"(src));
}
__device__ __forceinline__ void cp_commit() {
    asm volatile("cp.async.commit_group;");
}
template<int N> __device__ __forceinline__ void cp_wait() {
    asm volatile("cp.async.wait_group %0;" :: "n"(N));
}

// ---------------------------------------------------------------------------
// Merged pre-round + fragment-swizzle pass (unchanged).
// ---------------------------------------------------------------------------
#define NX4 (Mm*Ee/4)
#define NW4 (Hh*Ee*Dd/4)
__global__ __launch_bounds__(256)
void round_all(const float4* __restrict__ x,  const float4* __restrict__ wq,
               const float4* __restrict__ wk, const float4* __restrict__ wv,
               const float4* __restrict__ wo)
{
    int i = blockIdx.x * 256 + threadIdx.x;
    if (i < NX4) {
        float4 v = cvt4(x[i]);
        const int m = (i << 2) >> 10;
        const int k = (i << 2) & 1023;
        float* p = g_xr + ((size_t)(m >> 4) * (Ee >> 3) + (k >> 3)) * 128
                 + ((m & 7) * 4) * 4 + ((m >> 3) & 1) + 2 * ((k >> 2) & 1);
        p[0] = v.x; p[4] = v.y; p[8] = v.z; p[12] = v.w;
        return;
    }
    i -= NX4;
    const int seg = i >> 18;
    const int j = i & (NW4 - 1);
    if (seg < 3) {
        const float4 v = cvt4(seg == 0 ? wq[j] : (seg == 1 ? wk[j] : wv[j]));
        float* dst = seg == 0 ? g_wqr : (seg == 1 ? g_wkr : g_wvr);
        const int elem = j << 2;
        const int h = elem >> 16;
        const int rem = elem & 65535;
        const int k = rem >> 6;
        const int n = h * 64 + (rem & 63);
        float* p = dst + ((size_t)(n >> 3) * (Ee >> 3) + (k >> 3)) * 64
                 + ((n & 7) * 4 + (k & 3)) * 2 + ((k >> 2) & 1);
        p[0] = v.x; p[8] = v.y; p[16] = v.z; p[24] = v.w;
    } else {
        const float4 v = cvt4(wo[j]);
        const int elem = j << 2;
        const int k = elem >> 10;
        const int n = elem & 1023;
        float* p = g_wor + ((size_t)(n >> 3) * (Nn >> 3) + (k >> 3)) * 64
                 + ((n & 7) * 4 + (k & 3)) * 2 + ((k >> 2) & 1);
        p[0] = v.x; p[8] = v.y; p[16] = v.z; p[24] = v.w;
    }
}

// ---------------------------------------------------------------------------
// GEMM config (both GEMMs identical structure)
// ---------------------------------------------------------------------------
#define KC 32
#define ABYTES 16384
#define BBYTES 16384
#define STG (ABYTES+BBYTES)
#define GEMM_SMEM (3*STG)

// ---------------------------------------------------------------------------
// Kernel 1: QKV projection (unchanged; writes q/k/v in frag-tile order)
// ---------------------------------------------------------------------------
__global__ __launch_bounds__(256, 2)
void proj_mma(const float* __restrict__ bq, const float* __restrict__ bk,
              const float* __restrict__ bv)
{
    extern __shared__ float sm[];
    const uint32_t sb = smem_u32(sm);
    const int sel = blockIdx.z;
    const float* W    = sel == 0 ? g_wqr : (sel == 1 ? g_wkr : g_wvr);
    const float* bias = sel == 0 ? bq    : (sel == 1 ? bk    : bv);

    const int t = threadIdx.x, lane = t & 31, wid = t >> 5;
    const int q = lane & 3, g = lane >> 2;
    const int wm4 = (wid & 1) * 4;
    const int wn4 = (wid >> 1) * 4;
    const int n0 = blockIdx.x * 128, m0 = blockIdx.y * 128;

    float acc[4][4][4];
    #pragma unroll
    for (int i = 0; i < 4; i++)
        #pragma unroll
        for (int j = 0; j < 4; j++)
            #pragma unroll
            for (int kk = 0; kk < 4; kk++) acc[i][j][kk] = 0.f;

    auto issue = [&](int k0, int s) {
        const uint32_t Ab = sb + s * STG;
        const uint32_t Bbse = Ab + ABYTES;
        #pragma unroll
        for (int j = 0; j < 4; j++) {
            const int idx = t + 256 * j;
            const int aseg = idx >> 7, aoff = idx & 127;
            cpa(Ab + idx * 16,
                g_xr + ((size_t)((m0 >> 4) + aseg) * (Ee >> 3) + (k0 >> 3)) * 128
                     + aoff * 4);
            const int bseg = idx >> 6, boff = idx & 63;
            cpa(Bbse + idx * 16,
                W + ((size_t)((n0 >> 3) + bseg) * (Ee >> 3) + (k0 >> 3)) * 64
                  + boff * 4);
        }
        cp_commit();
    };
    auto compute = [&](int s) {
        const uint32_t* A = (const uint32_t*)(sm + s * (STG / 4));
        const uint32_t* B = A + ABYTES / 4;
        #pragma unroll
        for (int ks = 0; ks < 4; ks++) {
            uint4 a4[4];
            #pragma unroll
            for (int mt = 0; mt < 4; mt++)
                a4[mt] = *(const uint4*)(A + ((wm4 + mt) * 4 + ks) * 128 + lane * 4);
            #pragma unroll
            for (int nt = 0; nt < 4; nt++) {
                const uint2 b2 = *(const uint2*)(B + ((wn4 + nt) * 4 + ks) * 64 + lane * 2);
                const uint32_t bf[2] = {b2.x, b2.y};
                #pragma unroll
                for (int mt = 0; mt < 4; mt++)
                    mma_tf32(acc[mt][nt], (const uint32_t*)&a4[mt], bf);
            }
        }
    };

    const int NC = Ee / KC;
    issue(0, 0);
    issue(KC, 1);
    for (int c = 0; c < NC; c++) {
        if (c + 1 < NC) cp_wait<1>(); else cp_wait<0>();
        __syncthreads();
        if (c + 2 < NC) issue((c + 2) * KC, (c + 2) % 3);
        compute(c % 3);
    }

    #pragma unroll
    for (int mt = 0; mt < 4; mt++) {
        #pragma unroll
        for (int rr = 0; rr < 2; rr++) {
            const int r_g = m0 + (wid & 1) * 64 + mt * 16 + g + rr * 8;
            const int bi = r_g >> 11, s = r_g & 2047;
            #pragma unroll
            for (int nt = 0; nt < 4; nt++) {
                const int n_g = n0 + (wid >> 1) * 32 + nt * 8 + 2 * q;
                const int h = n_g >> 6, d = n_g & 63;
                const size_t bh_off = (size_t)(bi * Hh + h) * Ss * Dd;
                float vx = acc[mt][nt][2*rr + 0] + bias[n_g];
                float vy = acc[mt][nt][2*rr + 1] + bias[n_g + 1];
                if (sel == 0) {
                    float* p = g_q + bh_off
                        + ((size_t)(s >> 4) * (Dd >> 3) + (d >> 3)) * 128
                        + ((s & 7) * 4 + (d & 3)) * 4 + ((s >> 3) & 1)
                        + 2 * ((d >> 2) & 1);
                    p[0] = tf32r(vx * QSCL);
                    p[4] = tf32r(vy * QSCL);
                } else if (sel == 1) {
                    float* p = g_k + bh_off
                        + ((size_t)(s >> 3) * (Dd >> 3) + (d >> 3)) * 64
                        + ((s & 7) * 4 + (d & 3)) * 2 + ((d >> 2) & 1);
                    p[0] = tf32r(vx);
                    p[2] = tf32r(vy);
                } else {
                    float* p = g_v + bh_off
                        + ((size_t)(d >> 3) * (Ss >> 3) + (s >> 3)) * 64
                        + ((d & 7) * 4 + (s & 3)) * 2 + ((s >> 2) & 1);
                    p[0] = tf32r(vx);
                    p[8] = tf32r(vy);
                }
            }
        }
    }
}

// ---------------------------------------------------------------------------
// Kernel 3: output projection — A frag-ordered from g_z (clone of proj).
// ---------------------------------------------------------------------------
__global__ __launch_bounds__(256, 2)
void outproj_mma(const float* __restrict__ bo, float* __restrict__ outp)
{
    extern __shared__ float sm[];
    const uint32_t sb = smem_u32(sm);
    const int t = threadIdx.x, lane = t & 31, wid = t >> 5;
    const int q = lane & 3, g = lane >> 2;
    const int wm4 = (wid & 1) * 4;
    const int wn4 = (wid >> 1) * 4;
    const int e0 = blockIdx.x * 128, m0 = blockIdx.y * 128;
    const int bi = m0 >> 11, s0 = m0 & 2047;

    float acc[4][4][4];
    #pragma unroll
    for (int i = 0; i < 4; i++)
        #pragma unroll
        for (int j = 0; j < 4; j++)
            #pragma unroll
            for (int kk = 0; kk < 4; kk++) acc[i][j][kk] = 0.f;

    auto issue = [&](int k0, int s) {
        const uint32_t Ab = sb + s * STG;
        const uint32_t Bbse = Ab + ABYTES;
        const int h = k0 >> 6, d0 = k0 & 63;
        const float* zb = g_z + (size_t)(bi * Hh + h) * Ss * Dd;
        #pragma unroll
        for (int j = 0; j < 4; j++) {
            const int idx = t + 256 * j;
            const int aseg = idx >> 7, aoff = idx & 127;
            cpa(Ab + idx * 16,
                zb + ((size_t)(((s0 >> 4) + aseg) * (Dd >> 3)) + (d0 >> 3)) * 128
                   + aoff * 4);
            const int bseg = idx >> 6, boff = idx & 63;
            cpa(Bbse + idx * 16,
                g_wor + ((size_t)((e0 >> 3) + bseg) * (Nn >> 3) + (k0 >> 3)) * 64
                      + boff * 4);
        }
        cp_commit();
    };
    auto compute = [&](int s) {
        const uint32_t* A = (const uint32_t*)(sm + s * (STG / 4));
        const uint32_t* B = A + ABYTES / 4;
        #pragma unroll
        for (int ks = 0; ks < 4; ks++) {
            uint4 a4[4];
            #pragma unroll
            for (int mt = 0; mt < 4; mt++)
                a4[mt] = *(const uint4*)(A + ((wm4 + mt) * 4 + ks) * 128 + lane * 4);
            #pragma unroll
            for (int nt = 0; nt < 4; nt++) {
                const uint2 b2 = *(const uint2*)(B + ((wn4 + nt) * 4 + ks) * 64 + lane * 2);
                const uint32_t bf[2] = {b2.x, b2.y};
                #pragma unroll
                for (int mt = 0; mt < 4; mt++)
                    mma_tf32(acc[mt][nt], (const uint32_t*)&a4[mt], bf);
            }
        }
    };

    const int NC = Nn / KC;
    issue(0, 0);
    issue(KC, 1);
    for (int c = 0; c < NC; c++) {
        if (c + 1 < NC) cp_wait<1>(); else cp_wait<0>();
        __syncthreads();
        if (c + 2 < NC) issue((c + 2) * KC, (c + 2) % 3);
        compute(c % 3);
    }

    #pragma unroll
    for (int mt = 0; mt < 4; mt++) {
        #pragma unroll
        for (int rr = 0; rr < 2; rr++) {
            const int r_g = m0 + (wid & 1) * 64 + mt * 16 + g + rr * 8;
            #pragma unroll
            for (int nt = 0; nt < 4; nt++) {
                const int e = e0 + (wid >> 1) * 32 + nt * 8 + 2 * q;
                float2 v;
                v.x = acc[mt][nt][2*rr + 0] + bo[e];
                v.y = acc[mt][nt][2*rr + 1] + bo[e + 1];
                *(float2*)(outp + (size_t)r_g * Ee + e) = v;
            }
        }
    }
}

// ---------------------------------------------------------------------------
// Kernel 2: flash attention, 2 CTAs/SM (loop identical to 789us best).
// Epilogue: stage z tile in P smem (frag order, warp-private), then
// fully coalesced STG.128 block copy to g_z.
// ---------------------------------------------------------------------------
#define APITCH 68
#define AROWS 128
#define PFL (AROWS*APITCH)         // 8704 floats (>= 8192 staging floats)
#define KVT 4096
#define FO_P  0
#define FO_K0 PFL
#define FO_V0 (FO_K0 + KVT)
#define FO_K1 (FO_V0 + KVT)
#define FO_V1 (FO_K1 + KVT)
#define ATTN_SMEM ((PFL + 4*KVT)*4)   // 100352 bytes

__global__ __launch_bounds__(256, 2)
void attn_mma()
{
    extern __shared__ float sm[];
    const uint32_t sb = smem_u32(sm);
    const int t = threadIdx.x, lane = t & 31, wid = t >> 5;
    const int q = lane & 3, g = lane >> 2;
    const int bh = blockIdx.y;
    const int row0 = blockIdx.x * AROWS;
    const size_t bhoff = (size_t)bh * Ss * Dd;
    const int wr = wid * 16;

    uint32_t* Pu = (uint32_t*)sm + FO_P;
    float* Ps = sm + FO_P;

    auto issueKV = [&](int t0, int s) {
        const uint32_t Kb = sb + (s ? FO_K1 : FO_K0) * 4;
        const uint32_t Vb = sb + (s ? FO_V1 : FO_V0) * 4;
        #pragma unroll
        for (int j = 0; j < 4; j++) {
            const int idx = t + 256 * j;
            cpa(Kb + idx * 16, g_k + bhoff + (size_t)t0 * 64 + idx * 4);
            const int dt = idx >> 7, rem = idx & 127;
            cpa(Vb + idx * 16,
                g_v + bhoff + ((size_t)dt * (Ss >> 3) + (t0 >> 3)) * 64 + rem * 4);
        }
        cp_commit();
    };

    // Q fragments straight into registers
    uint4 qf[8];
    {
        const float* qb = g_q + bhoff + (size_t)((row0 >> 4) + wid) * 8 * 128;
        #pragma unroll
        for (int ks = 0; ks < 8; ks++)
            qf[ks] = *(const uint4*)(qb + ks * 128 + lane * 4);
    }

    issueKV(0, 0);

    float lR[2] = {0.f, 0.f};
    float o[8][4];
    #pragma unroll
    for (int nt = 0; nt < 8; nt++)
        #pragma unroll
        for (int c = 0; c < 4; c++) o[nt][c] = 0.f;

    const int NT = Ss / 64;
    for (int it = 0; it < NT; it++) {
        cp_wait<0>();
        __syncthreads();
        const int buf = it & 1;
        if (it + 1 < NT) issueKV((it + 1) * 64, buf ^ 1);

        const uint32_t* Ku = (const uint32_t*)sm + (buf ? FO_K1 : FO_K0);
        const uint32_t* Vu = (const uint32_t*)sm + (buf ? FO_V1 : FO_V0);

        float s[8][4];
        #pragma unroll
        for (int nt = 0; nt < 8; nt++)
            #pragma unroll
            for (int c = 0; c < 4; c++) s[nt][c] = 0.f;
        #pragma unroll
        for (int ks = 0; ks < 8; ks++) {
            #pragma unroll
            for (int nt = 0; nt < 8; nt++) {
                const uint2 b2 = *(const uint2*)(Ku + (nt * 8 + ks) * 64 + lane * 2);
                const uint32_t bf[2] = {b2.x, b2.y};
                mma_tf32(s[nt], (const uint32_t*)&qf[ks], bf);
            }
        }

        #pragma unroll
        for (int rr = 0; rr < 2; rr++) {
            const int prow = wr + rr * 8 + g;
            float sum = 0.f;
            #pragma unroll
            for (int nt = 0; nt < 8; nt++) {
                float p0 = tf32r(ex2(s[nt][2*rr]));
                float p1 = tf32r(ex2(s[nt][2*rr+1]));
                sum += p0 + p1;
                float2 v; v.x = p0; v.y = p1;
                *(float2*)(Ps + prow * APITCH + nt * 8 + 2 * q) = v;
            }
            lR[rr] += sum;
        }
        __syncwarp();

        #pragma unroll
        for (int ks = 0; ks < 8; ks++) {
            const int ko = ks * 8;
            uint32_t af[4];
            af[0] = Pu[(wr + g) * APITCH + ko + q];
            af[1] = Pu[(wr + 8 + g) * APITCH + ko + q];
            af[2] = Pu[(wr + g) * APITCH + ko + q + 4];
            af[3] = Pu[(wr + 8 + g) * APITCH + ko + q + 4];
            #pragma unroll
            for (int nt = 0; nt < 8; nt++) {
                const uint2 b2 = *(const uint2*)(Vu + (nt * 8 + ks) * 64 + lane * 2);
                const uint32_t bf[2] = {b2.x, b2.y};
                mma_tf32(o[nt], af, bf);
            }
        }
    }

    // Reduce denominators, normalize.
    #pragma unroll
    for (int i = 0; i < 2; i++) {
        lR[i] += __shfl_xor_sync(0xffffffffu, lR[i], 1);
        lR[i] += __shfl_xor_sync(0xffffffffu, lR[i], 2);
    }

    // Stage z tile into P smem (frag order; each warp writes only its own
    // tiles [wid*8 + nt], so no pre-sync needed).
    __syncthreads();   // all warps done reading P from last PV
    #pragma unroll
    for (int rr = 0; rr < 2; rr++) {
        const float inv = 1.0f / lR[rr];
        #pragma unroll
        for (int nt = 0; nt < 8; nt++) {
            const int base = (wid * 8 + nt) * 128
                           + (g * 4 + ((2 * q) & 3)) * 4 + rr + 2 * (q >> 1);
            Ps[base]     = tf32r(o[nt][2*rr]   * inv);
            Ps[base + 4] = tf32r(o[nt][2*rr+1] * inv);
        }
    }
    __syncthreads();

    // Coalesced copy: CTA's z region is contiguous (8192 floats) in frag layout
    float* zdst = g_z + bhoff + (size_t)row0 * 64;
    #pragma unroll
    for (int j = 0; j < 8; j++) {
        const int idx = t + 256 * j;              // float4 units, 0..2047
        *(float4*)(zdst + idx * 4) = *(const float4*)(Ps + idx * 4);
    }
}

// ---------------------------------------------------------------------------
extern "C" void kernel_launch(void* const* d_in, const int* in_sizes, int n_in,
                              void* d_out, int out_size)
{
    const float* x  = (const float*)d_in[0];
    const float* Wq = (const float*)d_in[1];
    const float* bq = (const float*)d_in[2];
    const float* Wk = (const float*)d_in[3];
    const float* bk = (const float*)d_in[4];
    const float* Wv = (const float*)d_in[5];
    const float* bv = (const float*)d_in[6];
    const float* Wo = (const float*)d_in[7];
    const float* bo = (const float*)d_in[8];
    float* out = (float*)d_out;

    cudaFuncSetAttribute(proj_mma,
                         cudaFuncAttributeMaxDynamicSharedMemorySize, GEMM_SMEM);
    cudaFuncSetAttribute(outproj_mma,
                         cudaFuncAttributeMaxDynamicSharedMemorySize, GEMM_SMEM);
    cudaFuncSetAttribute(attn_mma,
                         cudaFuncAttributeMaxDynamicSharedMemorySize, ATTN_SMEM);

    const int ntot = NX4 + 4 * NW4;
    round_all<<<(ntot + 255)/256, 256>>>((const float4*)x, (const float4*)Wq,
                                         (const float4*)Wk, (const float4*)Wv,
                                         (const float4*)Wo);

    proj_mma<<<dim3(Nn/128, Mm/128, 3), 256, GEMM_SMEM>>>(bq, bk, bv);
    attn_mma<<<dim3(Ss/AROWS, Bb*Hh), 256, ATTN_SMEM>>>();
    outproj_mma<<<dim3(Ee/128, Mm/128), 256, GEMM_SMEM>>>(bo, out);
}